// round 5
// baseline (speedup 1.0000x reference)
#include <cuda_runtime.h>
#include <math.h>

#define FDIM 64
#define NMAX 100000
#define EMAX 1600000
#define BGR  64

typedef unsigned long long ull;
typedef unsigned int uint;

// ---------------- f32x2 / tf32 helpers ----------------
__device__ __forceinline__ void fma2(ull& acc, ull a, ull b) {
    asm("fma.rn.f32x2 %0, %1, %2, %0;" : "+l"(acc) : "l"(a), "l"(b));
}
__device__ __forceinline__ void add2(ull& acc, ull a) {
    asm("add.rn.f32x2 %0, %1, %0;" : "+l"(acc) : "l"(a));
}
__device__ __forceinline__ ull bpack(float f) {
    ull o; unsigned u = __float_as_uint(f);
    asm("mov.b64 %0, {%1, %1};" : "=l"(o) : "r"(u));
    return o;
}
__device__ __forceinline__ ull pack2(float lo, float hi) {
    ull o;
    asm("mov.b64 %0, {%1, %2};" : "=l"(o) : "r"(__float_as_uint(lo)), "r"(__float_as_uint(hi)));
    return o;
}
__device__ __forceinline__ void unpack2(ull v, float& lo, float& hi) {
    unsigned a, b;
    asm("mov.b64 {%0, %1}, %2;" : "=r"(a), "=r"(b) : "l"(v));
    lo = __uint_as_float(a); hi = __uint_as_float(b);
}
__device__ __forceinline__ float tf32r(float x) {
    float r; asm("cvt.rna.tf32.f32 %0, %1;" : "=f"(r) : "f"(x)); return r;
}
__device__ __forceinline__ void mma_tf32(float* d, const uint* a, const uint* b) {
    asm volatile("mma.sync.aligned.m16n8k8.row.col.f32.tf32.tf32.f32 "
        "{%0,%1,%2,%3}, {%4,%5,%6,%7}, {%8,%9}, {%0,%1,%2,%3};"
        : "+f"(d[0]), "+f"(d[1]), "+f"(d[2]), "+f"(d[3])
        : "r"(a[0]), "r"(a[1]), "r"(a[2]), "r"(a[3]), "r"(b[0]), "r"(b[1]));
}
// A-fragment permutation: channel j within group of 8 -> (j&3)*2 + (j>>2)
__host__ __device__ __forceinline__ int permA(int c) {
    return ((c >> 3) << 3) + ((c & 3) << 1) + ((c >> 2) & 1);
}

// ---------------- device scratch ----------------
__device__ __align__(16) float g_C  [NMAX * FDIM];
__device__ __align__(16) float g_ys [NMAX * FDIM];
__device__ __align__(16) float g_zx [NMAX * FDIM];
__device__ __align__(16) float g_Ahi[(size_t)NMAX * 256];
__device__ __align__(16) float g_Alo[(size_t)NMAX * 256];
__device__ float g_amp [NMAX];
__device__ float g_iamp[NMAX];
__device__ __align__(16) float g_out[NMAX * FDIM];
__device__ int   g_cnt [NMAX];
__device__ int   g_offs[NMAX];
__device__ int   g_fill[NMAX];
__device__ int2  g_csr [EMAX];
__device__ int   g_cursor;
__device__ __align__(16) float g_WoWl[832 * FDIM];
__device__ __align__(16) float g_Bhi[3 * 256 * FDIM];
__device__ __align__(16) float g_Blo[3 * 256 * FDIM];
__device__ __align__(16) float g_Md[32 * FDIM], g_Ms[32 * FDIM], g_Mx[32 * FDIM];
__device__ __align__(16) float g_Wec[16 * FDIM];
__device__ float g_Cc[FDIM], g_csv[FDIM], g_cxv[FDIM];
__device__ float g_bnS[FDIM], g_bnQ[FDIM], g_bnA[FDIM], g_bnB[FDIM];
__device__ float g_pool[BGR * FDIM];

// ---------------- init ----------------
__global__ void k_init(int Nn) {
    int i = blockIdx.x * blockDim.x + threadIdx.x;
    if (i < Nn) g_cnt[i] = 0;
    if (i < BGR * FDIM) g_pool[i] = 0.f;
    if (i < FDIM) { g_bnS[i] = 0.f; g_bnQ[i] = 0.f; }
    if (i == 0) g_cursor = 0;
}

// ---------------- WoWl = Wo @ Wl  (832x64) ----------------
__global__ void k_wowl(const float* __restrict__ Wo, const float* __restrict__ Wl) {
    int idx = blockIdx.x * blockDim.x + threadIdx.x;
    if (idx >= 832 * FDIM) return;
    int r = idx >> 6, c = idx & 63;
    float a = 0.f;
    #pragma unroll
    for (int k = 0; k < FDIM; k++) a += Wo[r * FDIM + k] * Wl[k * FDIM + c];
    g_WoWl[idx] = a;
}

// ---------------- B-fragment permuted hi/lo weight copy ----------------
// idx = (((m*32 + s)*8 + t)*8 + n)*8 + q*2 + pair
// val = WoWl[64 + m*256 + 8s + q + 4*pair][8t + n]
__global__ void k_bprep() {
    int idx = blockIdx.x * blockDim.x + threadIdx.x;
    if (idx >= 3 * 256 * FDIM) return;
    int pair = idx & 1;
    int q = (idx >> 1) & 3;
    int n = (idx >> 3) & 7;
    int t = (idx >> 6) & 7;
    int s = (idx >> 9) & 31;
    int m = idx >> 14;
    int row = 64 + m * 256 + 8 * s + q + 4 * pair;
    int col = 8 * t + n;
    float v = g_WoWl[row * 64 + col];
    float hi = tf32r(v);
    g_Bhi[idx] = hi;
    g_Blo[idx] = tf32r(v - hi);
}

// ---------------- small folded-weight precompute ----------------
__global__ void k_small(const float* __restrict__ W2, const float* __restrict__ b2,
                        const float* __restrict__ Wp, const float* __restrict__ bp,
                        const float* __restrict__ We, const float* __restrict__ be,
                        const float* __restrict__ bo, const float* __restrict__ Wl,
                        const float* __restrict__ bl) {
    int idx = blockIdx.x * blockDim.x + threadIdx.x;
    if (idx < 2048) {
        int i = idx >> 6, c = idx & 63; float a = 0.f;
        #pragma unroll
        for (int k = 0; k < 64; k++) a += W2[i * 64 + k] * Wp[k * 64 + c];
        g_Md[idx] = a;
    } else if (idx < 4096) {
        int t = idx - 2048; int i = t >> 6, c = t & 63; float a = 0.f;
        #pragma unroll
        for (int k = 0; k < 64; k++) a += W2[i * 64 + k] * Wp[(64 + k) * 64 + c];
        g_Ms[t] = a;
    } else if (idx < 6144) {
        int t = idx - 4096; int i = t >> 6, c = t & 63; float a = 0.f;
        #pragma unroll
        for (int k = 0; k < 64; k++) a += W2[i * 64 + k] * g_WoWl[k * 64 + c];
        g_Mx[t] = a;
    } else if (idx < 7168) {
        int t = idx - 6144; int i = t >> 6, c = t & 63; float a = 0.f;
        #pragma unroll
        for (int k = 0; k < 64; k++) a += We[i * 64 + k] * Wp[(128 + k) * 64 + c];
        g_Wec[t] = a;
    } else if (idx < 7232) {
        int c = idx - 7168; float a = bp[c];
        #pragma unroll
        for (int k = 0; k < 64; k++) a += be[k] * Wp[(128 + k) * 64 + c] + b2[k] * Wp[k * 64 + c];
        g_Cc[c] = a;
    } else if (idx < 7296) {
        int c = idx - 7232; float a = 0.f;
        #pragma unroll
        for (int k = 0; k < 64; k++) a += b2[k] * Wp[(64 + k) * 64 + c];
        g_csv[c] = a;
    } else if (idx < 7360) {
        int c = idx - 7296; float a = bl[c];
        #pragma unroll
        for (int k = 0; k < 64; k++) a += bo[k] * Wl[k * 64 + c] + b2[k] * g_WoWl[k * 64 + c];
        g_cxv[c] = a;
    }
}

// ---------------- node pre-pass ----------------
__global__ __launch_bounds__(128) void k_node(const float* __restrict__ x,
                                              const float* __restrict__ W1,
                                              const float* __restrict__ b1, int Nn) {
    __shared__ __align__(16) float sW1[64 * 32];
    __shared__ __align__(16) float sM[3][32 * 64];
    __shared__ float sb1[32];
    __shared__ float sC[3][64];
    int tid = threadIdx.x;
    for (int i = tid; i < 64 * 32; i += 128) sW1[i] = W1[i];
    for (int i = tid; i < 32 * 64; i += 128) {
        sM[0][i] = g_Md[i]; sM[1][i] = g_Ms[i]; sM[2][i] = g_Mx[i];
    }
    if (tid < 32) sb1[tid] = b1[tid];
    if (tid < 64) { sC[0][tid] = g_Cc[tid]; sC[1][tid] = g_csv[tid]; sC[2][tid] = g_cxv[tid]; }
    __syncthreads();
    int n = blockIdx.x * 128 + tid;
    if (n >= Nn) return;

    ull tacc[16];
    #pragma unroll
    for (int j = 0; j < 16; j++) tacc[j] = pack2(sb1[2 * j], sb1[2 * j + 1]);
    const float4* xp = (const float4*)(x + (size_t)n * 64);
    #pragma unroll
    for (int i = 0; i < 16; i++) {
        float4 xv = xp[i];
        float xs[4] = {xv.x, xv.y, xv.z, xv.w};
        #pragma unroll
        for (int c = 0; c < 4; c++) {
            ull xb = bpack(xs[c]);
            const ulonglong2* wr = (const ulonglong2*)&sW1[(4 * i + c) * 32];
            #pragma unroll
            for (int q = 0; q < 8; q++) {
                ulonglong2 w = wr[q];
                fma2(tacc[2 * q], xb, w.x);
                fma2(tacc[2 * q + 1], xb, w.y);
            }
        }
    }
    float t[32];
    #pragma unroll
    for (int j = 0; j < 16; j++) {
        float lo, hi; unpack2(tacc[j], lo, hi);
        t[2 * j]     = fmaxf(lo, 0.f);
        t[2 * j + 1] = fmaxf(hi, 0.f);
    }

    float* outs[3];
    outs[0] = g_C  + (size_t)n * 64;
    outs[1] = g_ys + (size_t)n * 64;
    outs[2] = g_zx + (size_t)n * 64;
    #pragma unroll
    for (int m = 0; m < 3; m++) {
        #pragma unroll
        for (int h = 0; h < 2; h++) {
            ull acc[16];
            #pragma unroll
            for (int j = 0; j < 16; j++)
                acc[j] = pack2(sC[m][h * 32 + 2 * j], sC[m][h * 32 + 2 * j + 1]);
            #pragma unroll
            for (int k = 0; k < 32; k++) {
                ull tb = bpack(t[k]);
                const ulonglong2* wr = (const ulonglong2*)&sM[m][k * 64 + h * 32];
                #pragma unroll
                for (int q = 0; q < 8; q++) {
                    ulonglong2 w = wr[q];
                    fma2(acc[2 * q], tb, w.x);
                    fma2(acc[2 * q + 1], tb, w.y);
                }
            }
            float* op = outs[m] + h * 32;
            #pragma unroll
            for (int q = 0; q < 8; q++) {
                ulonglong2 v; v.x = acc[2 * q]; v.y = acc[2 * q + 1];
                *(ulonglong2*)(op + 4 * q) = v;
            }
        }
    }
}

// ---------------- CSR build ----------------
__global__ void k_count(const int* __restrict__ ei, int En) {
    int e = blockIdx.x * blockDim.x + threadIdx.x;
    if (e >= En) return;
    atomicAdd(&g_cnt[ei[En + e]], 1);
}

__global__ void k_scan(int Nn) {
    __shared__ int s[1024];
    __shared__ int base;
    int tid = threadIdx.x;
    int n = blockIdx.x * 1024 + tid;
    int c = (n < Nn) ? g_cnt[n] : 0;
    s[tid] = c;
    __syncthreads();
    for (int d = 1; d < 1024; d <<= 1) {
        int v = (tid >= d) ? s[tid - d] : 0;
        __syncthreads();
        s[tid] += v;
        __syncthreads();
    }
    if (tid == 1023) base = atomicAdd(&g_cursor, s[1023]);
    __syncthreads();
    if (n < Nn) {
        int off = base + s[tid] - c;
        g_offs[n] = off;
        g_fill[n] = off;
    }
}

__global__ void k_fill(const int* __restrict__ ei, int En) {
    int e = blockIdx.x * blockDim.x + threadIdx.x;
    if (e >= En) return;
    int d = ei[En + e];
    int s = ei[e];
    int p = atomicAdd(&g_fill[d], 1);
    g_csr[p] = make_int2(s, e);
}

// ---------------- aggregation: warp per node ----------------
__global__ __launch_bounds__(256) void k_agg(const float* __restrict__ ea, int Nn, float avg_log) {
    int lane = threadIdx.x & 31;
    int n = (blockIdx.x * 256 + threadIdx.x) >> 5;
    if (n >= Nn) return;

    ull wp[16];
    #pragma unroll
    for (int k = 0; k < 16; k++)
        wp[k] = pack2(g_Wec[k * 64 + lane], g_Wec[k * 64 + 32 + lane]);

    int off = g_offs[n];
    int d0 = g_cnt[n];
    ull s2 = 0ull, q2 = 0ull;
    float mn0 = 3.4e38f, mn1 = 3.4e38f, mx0 = -3.4e38f, mx1 = -3.4e38f;

    const float* yb = g_ys;
    for (int i = 0; i < d0; i++) {
        int2 se = g_csr[off + i];
        const float4* p = (const float4*)(ea + (size_t)se.y * 16);
        float4 a0 = p[0], a1 = p[1], a2 = p[2], a3 = p[3];
        const float* yp = yb + (size_t)se.x * 64;
        ull mA = pack2(yp[lane], yp[32 + lane]);
        ull mB = 0ull;
        fma2(mA, bpack(a0.x), wp[0]);  fma2(mB, bpack(a2.x), wp[8]);
        fma2(mA, bpack(a0.y), wp[1]);  fma2(mB, bpack(a2.y), wp[9]);
        fma2(mA, bpack(a0.z), wp[2]);  fma2(mB, bpack(a2.z), wp[10]);
        fma2(mA, bpack(a0.w), wp[3]);  fma2(mB, bpack(a2.w), wp[11]);
        fma2(mA, bpack(a1.x), wp[4]);  fma2(mB, bpack(a3.x), wp[12]);
        fma2(mA, bpack(a1.y), wp[5]);  fma2(mB, bpack(a3.y), wp[13]);
        fma2(mA, bpack(a1.z), wp[6]);  fma2(mB, bpack(a3.z), wp[14]);
        fma2(mA, bpack(a1.w), wp[7]);  fma2(mB, bpack(a3.w), wp[15]);
        add2(mA, mB);
        add2(s2, mA);
        fma2(q2, mA, mA);
        float m0, m1; unpack2(mA, m0, m1);
        mn0 = fminf(mn0, m0); mx0 = fmaxf(mx0, m0);
        mn1 = fminf(mn1, m1); mx1 = fmaxf(mx1, m1);
    }
    float s0, s1, q0, q1;
    unpack2(s2, s0, s1); unpack2(q2, q0, q1);

    float d = (float)((d0 > 1) ? d0 : 1);
    float inv_d = 1.f / d;
    float C0 = g_C[(size_t)n * 64 + lane], C1 = g_C[(size_t)n * 64 + 32 + lane];
    float mu0 = s0 * inv_d, mu1 = s1 * inv_d;
    float sd0 = sqrtf(fmaxf(q0 * inv_d - mu0 * mu0, 0.f) + 1e-5f);
    float sd1 = sqrtf(fmaxf(q1 * inv_d - mu1 * mu1, 0.f) + 1e-5f);
    float mean0, mean1;
    if (d0 > 0) {
        mean0 = mu0 + C0; mn0 += C0; mx0 += C0;
        mean1 = mu1 + C1; mn1 += C1; mx1 += C1;
    } else {
        mean0 = 0.f; mn0 = 0.f; mx0 = 0.f;
        mean1 = 0.f; mn1 = 0.f; mx1 = 0.f;
    }
    float amp = logf(d + 1.f) / avg_log;
    float iamp = 1.f / amp;

    float* Ah = g_Ahi + (size_t)n * 256;
    float* Al = g_Alo + (size_t)n * 256;
    float v[8];
    v[0] = mean0; v[1] = mean1; v[2] = mn0; v[3] = mn1;
    v[4] = mx0;   v[5] = mx1;   v[6] = sd0; v[7] = sd1;
    #pragma unroll
    for (int b = 0; b < 4; b++) {
        int p0 = permA(b * 64 + lane);
        int p1 = permA(b * 64 + 32 + lane);
        float h0 = tf32r(v[2 * b]);
        float h1 = tf32r(v[2 * b + 1]);
        Ah[p0] = h0; Al[p0] = tf32r(v[2 * b] - h0);
        Ah[p1] = h1; Al[p1] = tf32r(v[2 * b + 1] - h1);
    }
    if (lane == 0) { g_amp[n] = amp; g_iamp[n] = iamp; }
}

// ---------------- big GEMM via 3xTF32 mma.sync ----------------
// 256 threads = 8 warps (4 rowg x 2 colg); block tile 128 rows x 64 cols
__global__ __launch_bounds__(256) void k_gemm(int Nn) {
    __shared__ float sS[64], sQ[64];
    int tid = threadIdx.x, w = tid >> 5, l = tid & 31;
    if (tid < 64) { sS[tid] = 0.f; sQ[tid] = 0.f; }
    __syncthreads();
    int rowg = w >> 1, colg = w & 1;
    int rbase = blockIdx.x * 128 + rowg * 32;
    int cbase = colg * 32;
    int lr = l >> 2, lq = l & 3;

    float ampv[2][2], iampv[2][2];
    int rowidx[2][2];
    #pragma unroll
    for (int mt = 0; mt < 2; mt++) {
        int r0 = rbase + mt * 16 + lr;
        int c0 = min(r0, Nn - 1), c1 = min(r0 + 8, Nn - 1);
        rowidx[mt][0] = c0; rowidx[mt][1] = c1;
        ampv[mt][0] = g_amp[c0];  ampv[mt][1] = g_amp[c1];
        iampv[mt][0] = g_iamp[c0]; iampv[mt][1] = g_iamp[c1];
    }

    float acc[3][2][4][4];
    #pragma unroll
    for (int m = 0; m < 3; m++)
        #pragma unroll
        for (int mt = 0; mt < 2; mt++)
            #pragma unroll
            for (int nt = 0; nt < 4; nt++)
                #pragma unroll
                for (int j = 0; j < 4; j++) acc[m][mt][nt][j] = 0.f;

    for (int s = 0; s < 32; s++) {
        uint aH[2][4], aL[2][4];
        #pragma unroll
        for (int mt = 0; mt < 2; mt++) {
            size_t o0 = (size_t)rowidx[mt][0] * 256 + s * 8 + lq * 2;
            size_t o1 = (size_t)rowidx[mt][1] * 256 + s * 8 + lq * 2;
            float2 h0 = *(const float2*)&g_Ahi[o0];
            float2 h1 = *(const float2*)&g_Ahi[o1];
            float2 l0 = *(const float2*)&g_Alo[o0];
            float2 l1 = *(const float2*)&g_Alo[o1];
            aH[mt][0] = __float_as_uint(h0.x); aH[mt][1] = __float_as_uint(h1.x);
            aH[mt][2] = __float_as_uint(h0.y); aH[mt][3] = __float_as_uint(h1.y);
            aL[mt][0] = __float_as_uint(l0.x); aL[mt][1] = __float_as_uint(l1.x);
            aL[mt][2] = __float_as_uint(l0.y); aL[mt][3] = __float_as_uint(l1.y);
        }
        #pragma unroll
        for (int m = 0; m < 3; m++) {
            #pragma unroll
            for (int nt = 0; nt < 4; nt++) {
                int tg = colg * 4 + nt;
                size_t boff = ((((size_t)(m * 32 + s) * 8 + tg) * 8 + lr) * 8) + lq * 2;
                float2 bh = *(const float2*)&g_Bhi[boff];
                float2 bl = *(const float2*)&g_Blo[boff];
                uint bhR[2] = {__float_as_uint(bh.x), __float_as_uint(bh.y)};
                uint blR[2] = {__float_as_uint(bl.x), __float_as_uint(bl.y)};
                #pragma unroll
                for (int mt = 0; mt < 2; mt++) {
                    mma_tf32(acc[m][mt][nt], aH[mt], bhR);
                    mma_tf32(acc[m][mt][nt], aH[mt], blR);
                    mma_tf32(acc[m][mt][nt], aL[mt], bhR);
                }
            }
        }
    }

    float ls0[4] = {0, 0, 0, 0}, ls1[4] = {0, 0, 0, 0};
    float lq0[4] = {0, 0, 0, 0}, lq1[4] = {0, 0, 0, 0};
    #pragma unroll
    for (int mt = 0; mt < 2; mt++) {
        int r0 = rbase + mt * 16 + lr;
        int r1 = r0 + 8;
        #pragma unroll
        for (int nt = 0; nt < 4; nt++) {
            int c0 = cbase + nt * 8 + lq * 2;
            float o00 = acc[0][mt][nt][0] + ampv[mt][0] * acc[1][mt][nt][0] + iampv[mt][0] * acc[2][mt][nt][0];
            float o01 = acc[0][mt][nt][1] + ampv[mt][0] * acc[1][mt][nt][1] + iampv[mt][0] * acc[2][mt][nt][1];
            float o10 = acc[0][mt][nt][2] + ampv[mt][1] * acc[1][mt][nt][2] + iampv[mt][1] * acc[2][mt][nt][2];
            float o11 = acc[0][mt][nt][3] + ampv[mt][1] * acc[1][mt][nt][3] + iampv[mt][1] * acc[2][mt][nt][3];
            if (r0 < Nn) {
                float2 z = *(const float2*)&g_zx[(size_t)r0 * 64 + c0];
                o00 += z.x; o01 += z.y;
                float2 ov; ov.x = o00; ov.y = o01;
                *(float2*)&g_out[(size_t)r0 * 64 + c0] = ov;
                ls0[nt] += o00; lq0[nt] += o00 * o00;
                ls1[nt] += o01; lq1[nt] += o01 * o01;
            }
            if (r1 < Nn) {
                float2 z = *(const float2*)&g_zx[(size_t)r1 * 64 + c0];
                o10 += z.x; o11 += z.y;
                float2 ov; ov.x = o10; ov.y = o11;
                *(float2*)&g_out[(size_t)r1 * 64 + c0] = ov;
                ls0[nt] += o10; lq0[nt] += o10 * o10;
                ls1[nt] += o11; lq1[nt] += o11 * o11;
            }
        }
    }
    #pragma unroll
    for (int nt = 0; nt < 4; nt++) {
        int c0 = cbase + nt * 8 + lq * 2;
        atomicAdd(&sS[c0], ls0[nt]);     atomicAdd(&sQ[c0], lq0[nt]);
        atomicAdd(&sS[c0 + 1], ls1[nt]); atomicAdd(&sQ[c0 + 1], lq1[nt]);
    }
    __syncthreads();
    if (tid < 64) {
        atomicAdd(&g_bnS[tid], sS[tid]);
        atomicAdd(&g_bnQ[tid], sQ[tid]);
    }
}

// ---------------- BN finalize ----------------
__global__ void k_bn(const float* __restrict__ gamma, const float* __restrict__ beta, int Nn) {
    int f = threadIdx.x;
    if (f >= 64) return;
    float inv_n = 1.f / (float)Nn;
    float mu = g_bnS[f] * inv_n;
    float var = g_bnQ[f] * inv_n - mu * mu;
    float sc = gamma[f] * rsqrtf(var + 1e-5f);
    g_bnA[f] = sc;
    g_bnB[f] = beta[f] - mu * sc;
}

// ---------------- pooling ----------------
__global__ void k_pool(const int* __restrict__ batch, int Nn) {
    int f = threadIdx.x & 63;
    int g = threadIdx.x >> 6;
    int n0 = blockIdx.x * 1024;
    float sc = g_bnA[f], sh = g_bnB[f];
    float acc = 0.f;
    int cur = -1;
    for (int i = g; i < 1024; i += 4) {
        int n = n0 + i;
        if (n >= Nn) break;
        int b = batch[n];
        float v = fmaxf(g_out[(size_t)n * 64 + f] * sc + sh, 0.f);
        if (b != cur) {
            if (cur >= 0) atomicAdd(&g_pool[cur * 64 + f], acc);
            cur = b; acc = v;
        } else {
            acc += v;
        }
    }
    if (cur >= 0) atomicAdd(&g_pool[cur * 64 + f], acc);
}

// ---------------- head MLP ----------------
__global__ void k_head(const float* __restrict__ Wm1, const float* __restrict__ bm1,
                       const float* __restrict__ Wm2, const float* __restrict__ bm2,
                       float* __restrict__ outp) {
    __shared__ float sp[64];
    __shared__ float red[128];
    int b = blockIdx.x, j = threadIdx.x;
    if (j < 64) sp[j] = g_pool[b * 64 + j];
    __syncthreads();
    float v = 0.f;
    if (j < 100) {
        float a = bm1[j];
        #pragma unroll
        for (int k = 0; k < 64; k++) a += sp[k] * Wm1[k * 100 + j];
        v = fmaxf(a, 0.f) * Wm2[j];
    }
    red[j] = v;
    __syncthreads();
    for (int st = 64; st > 0; st >>= 1) {
        if (j < st) red[j] += red[j + st];
        __syncthreads();
    }
    if (j == 0) outp[b] = red[0] + bm2[0];
}

// ---------------- launch ----------------
extern "C" void kernel_launch(void* const* d_in, const int* in_sizes, int n_in,
                              void* d_out, int out_size) {
    const float* x    = (const float*)d_in[0];
    const float* ea   = (const float*)d_in[1];
    const int*   ei   = (const int*)  d_in[2];
    const int*   batch= (const int*)  d_in[3];
    const float* W1   = (const float*)d_in[4];
    const float* b1   = (const float*)d_in[5];
    const float* W2   = (const float*)d_in[6];
    const float* b2   = (const float*)d_in[7];
    const float* We   = (const float*)d_in[8];
    const float* be   = (const float*)d_in[9];
    const float* Wp   = (const float*)d_in[10];
    const float* bp   = (const float*)d_in[11];
    const float* Wo   = (const float*)d_in[12];
    const float* bo   = (const float*)d_in[13];
    const float* Wl   = (const float*)d_in[14];
    const float* bl   = (const float*)d_in[15];
    const float* gamma= (const float*)d_in[16];
    const float* beta = (const float*)d_in[17];
    const float* Wm1  = (const float*)d_in[18];
    const float* bm1  = (const float*)d_in[19];
    const float* Wm2  = (const float*)d_in[20];
    const float* bm2  = (const float*)d_in[21];

    int N = in_sizes[0] / FDIM;
    int E = in_sizes[1] / 16;

    static const double DEG[17] = {0,1000,2000,4000,8000,16000,24000,20000,12000,
                                   6000,3000,2000,1000,500,300,200,100};
    double snum = 0.0, sden = 0.0;
    for (int i = 0; i < 17; i++) { snum += log((double)i + 1.0) * DEG[i]; sden += DEG[i]; }
    float avg_log = (float)(snum / sden);

    int nb256 = (N + 255) / 256;
    int eb256 = (E + 255) / 256;

    k_init <<<nb256, 256>>>(N);
    k_wowl <<<(832 * FDIM + 255) / 256, 256>>>(Wo, Wl);
    k_bprep<<<(3 * 256 * FDIM + 255) / 256, 256>>>();
    k_small<<<(7360 + 255) / 256, 256>>>(W2, b2, Wp, bp, We, be, bo, Wl, bl);
    k_node <<<(N + 127) / 128, 128>>>(x, W1, b1, N);
    k_count<<<eb256, 256>>>(ei, E);
    k_scan <<<(N + 1023) / 1024, 1024>>>(N);
    k_fill <<<eb256, 256>>>(ei, E);
    k_agg  <<<(N + 7) / 8, 256>>>(ea, N, avg_log);
    k_gemm <<<(N + 127) / 128, 256>>>(N);
    k_bn   <<<1, 64>>>(gamma, beta, N);
    k_pool <<<(N + 1023) / 1024, 256>>>(batch, N);
    k_head <<<BGR, 128>>>(Wm1, bm1, Wm2, bm2, (float*)d_out);
}

// round 6
// speedup vs baseline: 1.2796x; 1.2796x over previous
#include <cuda_runtime.h>
#include <math.h>

#define FDIM 64
#define NMAX 100000
#define EMAX 1600000
#define BGR  64

typedef unsigned long long ull;

// ---------------- f32x2 helpers ----------------
__device__ __forceinline__ void fma2(ull& acc, ull a, ull b) {
    asm("fma.rn.f32x2 %0, %1, %2, %0;" : "+l"(acc) : "l"(a), "l"(b));
}
__device__ __forceinline__ void add2(ull& acc, ull a) {
    asm("add.rn.f32x2 %0, %1, %0;" : "+l"(acc) : "l"(a));
}
__device__ __forceinline__ ull bpack(float f) {
    ull o; unsigned u = __float_as_uint(f);
    asm("mov.b64 %0, {%1, %1};" : "=l"(o) : "r"(u));
    return o;
}
__device__ __forceinline__ ull pack2(float lo, float hi) {
    ull o;
    asm("mov.b64 %0, {%1, %2};" : "=l"(o) : "r"(__float_as_uint(lo)), "r"(__float_as_uint(hi)));
    return o;
}
__device__ __forceinline__ void unpack2(ull v, float& lo, float& hi) {
    unsigned a, b;
    asm("mov.b64 {%0, %1}, %2;" : "=r"(a), "=r"(b) : "l"(v));
    lo = __uint_as_float(a); hi = __uint_as_float(b);
}

// ---------------- device scratch ----------------
__device__ __align__(16) float g_C  [NMAX * FDIM];
__device__ __align__(16) float g_ys [NMAX * FDIM];
__device__ __align__(16) float g_zx [NMAX * FDIM];
__device__ __align__(16) float g_agg[(size_t)NMAX * 256];   // [mean|mn|mx|std]
__device__ float g_amp [NMAX];
__device__ float g_iamp[NMAX];
__device__ __align__(16) float g_out[NMAX * FDIM];
__device__ int   g_cnt [NMAX];
__device__ int   g_offs[NMAX];
__device__ int   g_fill[NMAX];
__device__ int2  g_csr [EMAX];
__device__ int   g_cursor;
__device__ __align__(16) float g_WoWl[832 * FDIM];
__device__ __align__(16) float g_Md[32 * FDIM], g_Ms[32 * FDIM], g_Mx[32 * FDIM];
__device__ __align__(16) float g_Wec[16 * FDIM];
__device__ float g_Cc[FDIM], g_csv[FDIM], g_cxv[FDIM];
__device__ float g_bnS[FDIM], g_bnQ[FDIM], g_bnA[FDIM], g_bnB[FDIM];
__device__ float g_pool[BGR * FDIM];

// ---------------- init ----------------
__global__ void k_init(int Nn) {
    int i = blockIdx.x * blockDim.x + threadIdx.x;
    if (i < Nn) g_cnt[i] = 0;
    if (i < BGR * FDIM) g_pool[i] = 0.f;
    if (i < FDIM) { g_bnS[i] = 0.f; g_bnQ[i] = 0.f; }
    if (i == 0) g_cursor = 0;
}

// ---------------- WoWl = Wo @ Wl  (832x64) ----------------
__global__ void k_wowl(const float* __restrict__ Wo, const float* __restrict__ Wl) {
    int idx = blockIdx.x * blockDim.x + threadIdx.x;
    if (idx >= 832 * FDIM) return;
    int r = idx >> 6, c = idx & 63;
    float a = 0.f;
    #pragma unroll
    for (int k = 0; k < FDIM; k++) a += Wo[r * FDIM + k] * Wl[k * FDIM + c];
    g_WoWl[idx] = a;
}

// ---------------- small folded-weight precompute ----------------
__global__ void k_small(const float* __restrict__ W2, const float* __restrict__ b2,
                        const float* __restrict__ Wp, const float* __restrict__ bp,
                        const float* __restrict__ We, const float* __restrict__ be,
                        const float* __restrict__ bo, const float* __restrict__ Wl,
                        const float* __restrict__ bl) {
    int idx = blockIdx.x * blockDim.x + threadIdx.x;
    if (idx < 2048) {                       // Md = W2 @ Wp[0:64]
        int i = idx >> 6, c = idx & 63; float a = 0.f;
        #pragma unroll
        for (int k = 0; k < 64; k++) a += W2[i * 64 + k] * Wp[k * 64 + c];
        g_Md[idx] = a;
    } else if (idx < 4096) {                // Ms = W2 @ Wp[64:128]
        int t = idx - 2048; int i = t >> 6, c = t & 63; float a = 0.f;
        #pragma unroll
        for (int k = 0; k < 64; k++) a += W2[i * 64 + k] * Wp[(64 + k) * 64 + c];
        g_Ms[t] = a;
    } else if (idx < 6144) {                // Mx = W2 @ WoWl[0:64]
        int t = idx - 4096; int i = t >> 6, c = t & 63; float a = 0.f;
        #pragma unroll
        for (int k = 0; k < 64; k++) a += W2[i * 64 + k] * g_WoWl[k * 64 + c];
        g_Mx[t] = a;
    } else if (idx < 7168) {                // Wec = We @ Wp[128:192]
        int t = idx - 6144; int i = t >> 6, c = t & 63; float a = 0.f;
        #pragma unroll
        for (int k = 0; k < 64; k++) a += We[i * 64 + k] * Wp[(128 + k) * 64 + c];
        g_Wec[t] = a;
    } else if (idx < 7232) {                // Cc = b2@WpA + be@WpC + bp
        int c = idx - 7168; float a = bp[c];
        #pragma unroll
        for (int k = 0; k < 64; k++) a += be[k] * Wp[(128 + k) * 64 + c] + b2[k] * Wp[k * 64 + c];
        g_Cc[c] = a;
    } else if (idx < 7296) {                // cs = b2@WpB
        int c = idx - 7232; float a = 0.f;
        #pragma unroll
        for (int k = 0; k < 64; k++) a += b2[k] * Wp[(64 + k) * 64 + c];
        g_csv[c] = a;
    } else if (idx < 7360) {                // cx = b2@WoWl[0:64] + bo@Wl + bl
        int c = idx - 7296; float a = bl[c];
        #pragma unroll
        for (int k = 0; k < 64; k++) a += bo[k] * Wl[k * 64 + c] + b2[k] * g_WoWl[k * 64 + c];
        g_cxv[c] = a;
    }
}

// ---------------- node pre-pass (round-2 scalar form, 79 regs) ----------------
__global__ __launch_bounds__(256) void k_node(const float* __restrict__ x,
                                              const float* __restrict__ W1,
                                              const float* __restrict__ b1, int Nn) {
    __shared__ float sW1[64 * 32];
    __shared__ float sM[3][32 * 64];
    __shared__ float sb1[32];
    __shared__ float sC[3][64];
    int tid = threadIdx.x;
    for (int i = tid; i < 64 * 32; i += 256) sW1[i] = W1[i];
    for (int i = tid; i < 32 * 64; i += 256) {
        sM[0][i] = g_Md[i]; sM[1][i] = g_Ms[i]; sM[2][i] = g_Mx[i];
    }
    if (tid < 32) sb1[tid] = b1[tid];
    if (tid < 64) { sC[0][tid] = g_Cc[tid]; sC[1][tid] = g_csv[tid]; sC[2][tid] = g_cxv[tid]; }
    __syncthreads();
    int n = blockIdx.x * 256 + tid;
    if (n >= Nn) return;

    float xr[64];
    const float4* xp = (const float4*)(x + (size_t)n * 64);
    #pragma unroll
    for (int i = 0; i < 16; i++) {
        float4 v = xp[i];
        xr[4*i] = v.x; xr[4*i+1] = v.y; xr[4*i+2] = v.z; xr[4*i+3] = v.w;
    }
    float t[32];
    #pragma unroll
    for (int j = 0; j < 32; j += 4) {
        float a0 = sb1[j], a1 = sb1[j+1], a2 = sb1[j+2], a3 = sb1[j+3];
        #pragma unroll
        for (int i = 0; i < 64; i++) {
            float xi = xr[i];
            const float* w = &sW1[i * 32 + j];
            a0 += xi * w[0]; a1 += xi * w[1]; a2 += xi * w[2]; a3 += xi * w[3];
        }
        t[j] = fmaxf(a0, 0.f); t[j+1] = fmaxf(a1, 0.f);
        t[j+2] = fmaxf(a2, 0.f); t[j+3] = fmaxf(a3, 0.f);
    }
    float* out0 = g_C  + (size_t)n * 64;
    float* out1 = g_ys + (size_t)n * 64;
    float* out2 = g_zx + (size_t)n * 64;
    #pragma unroll
    for (int m = 0; m < 3; m++) {
        float* op = (m == 0) ? out0 : (m == 1) ? out1 : out2;
        #pragma unroll
        for (int j = 0; j < 64; j += 4) {
            float a0 = sC[m][j], a1 = sC[m][j+1], a2 = sC[m][j+2], a3 = sC[m][j+3];
            #pragma unroll
            for (int i = 0; i < 32; i++) {
                float ti = t[i];
                const float* w = &sM[m][i * 64 + j];
                a0 += ti * w[0]; a1 += ti * w[1]; a2 += ti * w[2]; a3 += ti * w[3];
            }
            float4 v; v.x = a0; v.y = a1; v.z = a2; v.w = a3;
            *(float4*)(op + j) = v;
        }
    }
}

// ---------------- CSR build ----------------
__global__ void k_count(const int* __restrict__ ei, int En) {
    int e = blockIdx.x * blockDim.x + threadIdx.x;
    if (e >= En) return;
    atomicAdd(&g_cnt[ei[En + e]], 1);
}

__global__ void k_scan(int Nn) {
    __shared__ int s[1024];
    __shared__ int base;
    int tid = threadIdx.x;
    int n = blockIdx.x * 1024 + tid;
    int c = (n < Nn) ? g_cnt[n] : 0;
    s[tid] = c;
    __syncthreads();
    for (int d = 1; d < 1024; d <<= 1) {
        int v = (tid >= d) ? s[tid - d] : 0;
        __syncthreads();
        s[tid] += v;
        __syncthreads();
    }
    if (tid == 1023) base = atomicAdd(&g_cursor, s[1023]);
    __syncthreads();
    if (n < Nn) {
        int off = base + s[tid] - c;
        g_offs[n] = off;
        g_fill[n] = off;
    }
}

__global__ void k_fill(const int* __restrict__ ei, int En) {
    int e = blockIdx.x * blockDim.x + threadIdx.x;
    if (e >= En) return;
    int d = ei[En + e];
    int s = ei[e];
    int p = atomicAdd(&g_fill[d], 1);
    g_csr[p] = make_int2(s, e);
}

// ---------------- aggregation: warp per node ----------------
__global__ __launch_bounds__(256) void k_agg(const float* __restrict__ ea, int Nn, float avg_log) {
    int lane = threadIdx.x & 31;
    int n = (blockIdx.x * 256 + threadIdx.x) >> 5;
    if (n >= Nn) return;

    ull wp[16];
    #pragma unroll
    for (int k = 0; k < 16; k++)
        wp[k] = pack2(g_Wec[k * 64 + lane], g_Wec[k * 64 + 32 + lane]);

    int off = g_offs[n];
    int d0 = g_cnt[n];
    ull s2 = 0ull, q2 = 0ull;
    float mn0 = 3.4e38f, mn1 = 3.4e38f, mx0 = -3.4e38f, mx1 = -3.4e38f;

    const float* yb = g_ys;
    for (int i = 0; i < d0; i++) {
        int2 se = g_csr[off + i];
        const float4* p = (const float4*)(ea + (size_t)se.y * 16);
        float4 a0 = p[0], a1 = p[1], a2 = p[2], a3 = p[3];
        const float* yp = yb + (size_t)se.x * 64;
        ull mA = pack2(yp[lane], yp[32 + lane]);
        ull mB = 0ull;
        fma2(mA, bpack(a0.x), wp[0]);  fma2(mB, bpack(a2.x), wp[8]);
        fma2(mA, bpack(a0.y), wp[1]);  fma2(mB, bpack(a2.y), wp[9]);
        fma2(mA, bpack(a0.z), wp[2]);  fma2(mB, bpack(a2.z), wp[10]);
        fma2(mA, bpack(a0.w), wp[3]);  fma2(mB, bpack(a2.w), wp[11]);
        fma2(mA, bpack(a1.x), wp[4]);  fma2(mB, bpack(a3.x), wp[12]);
        fma2(mA, bpack(a1.y), wp[5]);  fma2(mB, bpack(a3.y), wp[13]);
        fma2(mA, bpack(a1.z), wp[6]);  fma2(mB, bpack(a3.z), wp[14]);
        fma2(mA, bpack(a1.w), wp[7]);  fma2(mB, bpack(a3.w), wp[15]);
        add2(mA, mB);
        add2(s2, mA);
        fma2(q2, mA, mA);
        float m0, m1; unpack2(mA, m0, m1);
        mn0 = fminf(mn0, m0); mx0 = fmaxf(mx0, m0);
        mn1 = fminf(mn1, m1); mx1 = fmaxf(mx1, m1);
    }
    float s0, s1, q0, q1;
    unpack2(s2, s0, s1); unpack2(q2, q0, q1);

    float d = (float)((d0 > 1) ? d0 : 1);
    float inv_d = 1.f / d;
    float C0 = g_C[(size_t)n * 64 + lane], C1 = g_C[(size_t)n * 64 + 32 + lane];
    float mu0 = s0 * inv_d, mu1 = s1 * inv_d;
    float sd0 = sqrtf(fmaxf(q0 * inv_d - mu0 * mu0, 0.f) + 1e-5f);
    float sd1 = sqrtf(fmaxf(q1 * inv_d - mu1 * mu1, 0.f) + 1e-5f);
    float mean0, mean1;
    if (d0 > 0) {
        mean0 = mu0 + C0; mn0 += C0; mx0 += C0;
        mean1 = mu1 + C1; mn1 += C1; mx1 += C1;
    } else {
        mean0 = 0.f; mn0 = 0.f; mx0 = 0.f;
        mean1 = 0.f; mn1 = 0.f; mx1 = 0.f;
    }
    float amp = logf(d + 1.f) / avg_log;
    float iamp = 1.f / amp;

    float* A = g_agg + (size_t)n * 256;
    A[lane]       = mean0; A[32 + lane]  = mean1;
    A[64 + lane]  = mn0;   A[96 + lane]  = mn1;
    A[128 + lane] = mx0;   A[160 + lane] = mx1;
    A[192 + lane] = sd0;   A[224 + lane] = sd1;
    if (lane == 0) { g_amp[n] = amp; g_iamp[n] = iamp; }
}

// ---------------- big GEMM: out = zx + agg@Wa + amp*(agg@Wb) + iamp*(agg@Wc) ----
// 128 threads; block tile 64 rows x 64 cols; thread tile 8 rows x 4 cols x 3 mats
#define GBM 64
#define GBK 32
__global__ __launch_bounds__(128) void k_gemm(int Nn) {
    __shared__ __align__(16) float sA[GBM * GBK];
    __shared__ __align__(16) float sW[3][GBK * 64];
    __shared__ float sS[64], sQ[64];
    int tid = threadIdx.x;
    if (tid < 64) { sS[tid] = 0.f; sQ[tid] = 0.f; }
    int bm = blockIdx.x * GBM;
    int tr8 = (tid >> 4) << 3;      // thread row base (0..56, step 8)
    int c4  = (tid & 15) << 2;      // col base (0..60, step 4)

    ull acc[3][8][2];
    #pragma unroll
    for (int m = 0; m < 3; m++)
        #pragma unroll
        for (int i = 0; i < 8; i++) { acc[m][i][0] = 0ull; acc[m][i][1] = 0ull; }

    const float* Wbase = g_WoWl + 64 * 64;  // [768,64]
    for (int k0 = 0; k0 < 256; k0 += GBK) {
        // load A tile: 64x32 = 512 float4 / 128 thr = 4 each
        #pragma unroll
        for (int l = 0; l < 4; l++) {
            int lin = tid + 128 * l;
            int r = lin >> 3, kq = (lin & 7) << 2;
            int row = bm + r;
            float4 vz = make_float4(0.f, 0.f, 0.f, 0.f);
            float4 vv = (row < Nn) ? *(const float4*)(g_agg + (size_t)row * 256 + k0 + kq) : vz;
            *(float4*)&sA[r * GBK + kq] = vv;
        }
        // load W tiles: 3 x 32x64 = 1536 float4 / 128 thr = 12 each
        #pragma unroll
        for (int l = 0; l < 12; l++) {
            int lin = tid + 128 * l;
            int m = lin >> 9, t2 = lin & 511;
            int k = t2 >> 4, cq = (t2 & 15) << 2;
            *(float4*)&sW[m][k * 64 + cq] =
                *(const float4*)(Wbase + (size_t)(m * 256 + k0 + k) * 64 + cq);
        }
        __syncthreads();
        #pragma unroll
        for (int kk = 0; kk < GBK; kk++) {
            ulonglong2 w0 = *(const ulonglong2*)&sW[0][kk * 64 + c4];
            ulonglong2 w1 = *(const ulonglong2*)&sW[1][kk * 64 + c4];
            ulonglong2 w2 = *(const ulonglong2*)&sW[2][kk * 64 + c4];
            #pragma unroll
            for (int i = 0; i < 8; i++) {
                ull a = bpack(sA[(tr8 + i) * GBK + kk]);
                fma2(acc[0][i][0], a, w0.x); fma2(acc[0][i][1], a, w0.y);
                fma2(acc[1][i][0], a, w1.x); fma2(acc[1][i][1], a, w1.y);
                fma2(acc[2][i][0], a, w2.x); fma2(acc[2][i][1], a, w2.y);
            }
        }
        __syncthreads();
    }

    // epilogue
    float lS[4] = {0.f, 0.f, 0.f, 0.f};
    float lQ[4] = {0.f, 0.f, 0.f, 0.f};
    #pragma unroll
    for (int i = 0; i < 8; i++) {
        int row = bm + tr8 + i;
        if (row < Nn) {
            float amp = g_amp[row], ia = g_iamp[row];
            float4 z = *(const float4*)(g_zx + (size_t)row * 64 + c4);
            float o[4];
            #pragma unroll
            for (int j = 0; j < 2; j++) {
                float A0, A1, B0, B1, Cv0, Cv1;
                unpack2(acc[0][i][j], A0, A1);
                unpack2(acc[1][i][j], B0, B1);
                unpack2(acc[2][i][j], Cv0, Cv1);
                o[2 * j]     = A0 + amp * B0 + ia * Cv0;
                o[2 * j + 1] = A1 + amp * B1 + ia * Cv1;
            }
            o[0] += z.x; o[1] += z.y; o[2] += z.z; o[3] += z.w;
            float4 ov; ov.x = o[0]; ov.y = o[1]; ov.z = o[2]; ov.w = o[3];
            *(float4*)(g_out + (size_t)row * 64 + c4) = ov;
            #pragma unroll
            for (int j = 0; j < 4; j++) { lS[j] += o[j]; lQ[j] += o[j] * o[j]; }
        }
    }
    #pragma unroll
    for (int j = 0; j < 4; j++) {
        atomicAdd(&sS[c4 + j], lS[j]);
        atomicAdd(&sQ[c4 + j], lQ[j]);
    }
    __syncthreads();
    if (tid < 64) {
        atomicAdd(&g_bnS[tid], sS[tid]);
        atomicAdd(&g_bnQ[tid], sQ[tid]);
    }
}

// ---------------- BN finalize ----------------
__global__ void k_bn(const float* __restrict__ gamma, const float* __restrict__ beta, int Nn) {
    int f = threadIdx.x;
    if (f >= 64) return;
    float inv_n = 1.f / (float)Nn;
    float mu = g_bnS[f] * inv_n;
    float var = g_bnQ[f] * inv_n - mu * mu;
    float sc = gamma[f] * rsqrtf(var + 1e-5f);
    g_bnA[f] = sc;
    g_bnB[f] = beta[f] - mu * sc;
}

// ---------------- pooling ----------------
__global__ void k_pool(const int* __restrict__ batch, int Nn) {
    int f = threadIdx.x & 63;
    int g = threadIdx.x >> 6;
    int n0 = blockIdx.x * 1024;
    float sc = g_bnA[f], sh = g_bnB[f];
    float acc = 0.f;
    int cur = -1;
    for (int i = g; i < 1024; i += 4) {
        int n = n0 + i;
        if (n >= Nn) break;
        int b = batch[n];
        float v = fmaxf(g_out[(size_t)n * 64 + f] * sc + sh, 0.f);
        if (b != cur) {
            if (cur >= 0) atomicAdd(&g_pool[cur * 64 + f], acc);
            cur = b; acc = v;
        } else {
            acc += v;
        }
    }
    if (cur >= 0) atomicAdd(&g_pool[cur * 64 + f], acc);
}

// ---------------- head MLP ----------------
__global__ void k_head(const float* __restrict__ Wm1, const float* __restrict__ bm1,
                       const float* __restrict__ Wm2, const float* __restrict__ bm2,
                       float* __restrict__ outp) {
    __shared__ float sp[64];
    __shared__ float red[128];
    int b = blockIdx.x, j = threadIdx.x;
    if (j < 64) sp[j] = g_pool[b * 64 + j];
    __syncthreads();
    float v = 0.f;
    if (j < 100) {
        float a = bm1[j];
        #pragma unroll
        for (int k = 0; k < 64; k++) a += sp[k] * Wm1[k * 100 + j];
        v = fmaxf(a, 0.f) * Wm2[j];
    }
    red[j] = v;
    __syncthreads();
    for (int st = 64; st > 0; st >>= 1) {
        if (j < st) red[j] += red[j + st];
        __syncthreads();
    }
    if (j == 0) outp[b] = red[0] + bm2[0];
}

// ---------------- launch ----------------
extern "C" void kernel_launch(void* const* d_in, const int* in_sizes, int n_in,
                              void* d_out, int out_size) {
    const float* x    = (const float*)d_in[0];
    const float* ea   = (const float*)d_in[1];
    const int*   ei   = (const int*)  d_in[2];
    const int*   batch= (const int*)  d_in[3];
    const float* W1   = (const float*)d_in[4];
    const float* b1   = (const float*)d_in[5];
    const float* W2   = (const float*)d_in[6];
    const float* b2   = (const float*)d_in[7];
    const float* We   = (const float*)d_in[8];
    const float* be   = (const float*)d_in[9];
    const float* Wp   = (const float*)d_in[10];
    const float* bp   = (const float*)d_in[11];
    const float* Wo   = (const float*)d_in[12];
    const float* bo   = (const float*)d_in[13];
    const float* Wl   = (const float*)d_in[14];
    const float* bl   = (const float*)d_in[15];
    const float* gamma= (const float*)d_in[16];
    const float* beta = (const float*)d_in[17];
    const float* Wm1  = (const float*)d_in[18];
    const float* bm1  = (const float*)d_in[19];
    const float* Wm2  = (const float*)d_in[20];
    const float* bm2  = (const float*)d_in[21];

    int N = in_sizes[0] / FDIM;
    int E = in_sizes[1] / 16;

    static const double DEG[17] = {0,1000,2000,4000,8000,16000,24000,20000,12000,
                                   6000,3000,2000,1000,500,300,200,100};
    double snum = 0.0, sden = 0.0;
    for (int i = 0; i < 17; i++) { snum += log((double)i + 1.0) * DEG[i]; sden += DEG[i]; }
    float avg_log = (float)(snum / sden);

    int nb256 = (N + 255) / 256;
    int eb256 = (E + 255) / 256;

    k_init <<<nb256, 256>>>(N);
    k_wowl <<<(832 * FDIM + 255) / 256, 256>>>(Wo, Wl);
    k_small<<<(7360 + 255) / 256, 256>>>(W2, b2, Wp, bp, We, be, bo, Wl, bl);
    k_node <<<nb256, 256>>>(x, W1, b1, N);
    k_count<<<eb256, 256>>>(ei, E);
    k_scan <<<(N + 1023) / 1024, 1024>>>(N);
    k_fill <<<eb256, 256>>>(ei, E);
    k_agg  <<<(N + 7) / 8, 256>>>(ea, N, avg_log);
    k_gemm <<<(N + GBM - 1) / GBM, 128>>>(N);
    k_bn   <<<1, 64>>>(gamma, beta, N);
    k_pool <<<(N + 1023) / 1024, 256>>>(batch, N);
    k_head <<<BGR, 128>>>(Wm1, bm1, Wm2, bm2, (float*)d_out);
}